// round 11
// baseline (speedup 1.0000x reference)
#include <cuda_runtime.h>
#include <cuda_fp16.h>
#include <cstdint>

#define NN  50000
#define EE  800000
#define FIN 500
#define HH  96

typedef unsigned long long ull;

// ================= device scratch =================
__device__ __half d_yh[(size_t)NN * HH];      // x @ W1, fp16
__device__ float  d_tf[(size_t)NN * 192];     // layer1 agg, [view1 96 | view2 96] fp32
__device__ __half d_gh[(size_t)NN * 192];     // layer2 pre-agg, [view1 96 | view2 96] fp16
__device__ int    d_degout[NN];
__device__ int    d_degin [NN];
__device__ float  d_nout[NN];
__device__ float  d_nin [NN];
__device__ int    d_rowptr[NN + 1];
__device__ int    d_cursor[NN];
__device__ int    d_csrc [EE];                // src per CSR slot (spmm2)
__device__ int4   d_edge [EE];                // {src, perm[src], w_bits, 0} (spmm1)
__device__ float  d_wmsum[HH];
__device__ float  d_bmsum;
// prepacked W1 fragments: [h(2)][chunk(8)][kstep(4)][ntile(12)][lane(32)] uint2
#define BFRAG_N 24576
__device__ uint2  d_Bfrag[BFRAG_N];
// prepacked W2 fragments: [h(2)][kstep(6)][ntile(12)][lane(32)] uint2
#define BFRAG2_N 4608
__device__ uint2  d_Bfrag2[BFRAG2_N];
// scan temporaries
#define SCAN_NB 196
__device__ int    d_bsum[SCAN_NB];
__device__ int    d_boff[SCAN_NB];

// ================= mma helpers =================
__device__ __forceinline__ uint32_t smem_u32(const void* p) {
    uint32_t a;
    asm("{ .reg .u64 t; cvta.to.shared.u64 t, %1; cvt.u32.u64 %0, t; }" : "=r"(a) : "l"(p));
    return a;
}
__device__ __forceinline__ void ldmx4(uint32_t* r, uint32_t addr) {
    asm volatile("ldmatrix.sync.aligned.m8n8.x4.shared.b16 {%0,%1,%2,%3}, [%4];"
        : "=r"(r[0]), "=r"(r[1]), "=r"(r[2]), "=r"(r[3]) : "r"(addr));
}
__device__ __forceinline__ void mma16816(float* d, const uint32_t* a, uint2 b) {
    asm volatile("mma.sync.aligned.m16n8k16.row.col.f32.f16.f16.f32 "
        "{%0,%1,%2,%3}, {%4,%5,%6,%7}, {%8,%9}, {%0,%1,%2,%3};"
        : "+f"(d[0]), "+f"(d[1]), "+f"(d[2]), "+f"(d[3])
        : "r"(a[0]), "r"(a[1]), "r"(a[2]), "r"(a[3]), "r"(b.x), "r"(b.y));
}

// ================= 0. prep: zero degrees, Wm row-sums =================
__global__ void k_prep(const float* __restrict__ Wm, const float* __restrict__ bm) {
    int i = blockIdx.x * blockDim.x + threadIdx.x;
    if (i < NN) { d_degout[i] = 0; d_degin[i] = 0; }
    if (blockIdx.x == 0 && threadIdx.x < HH) {
        float s = 0.f;
        #pragma unroll 4
        for (int j = 0; j < HH; j++) s += Wm[threadIdx.x * HH + j];
        d_wmsum[threadIdx.x] = s;
        if (threadIdx.x == 0) {
            float b = 0.f;
            for (int j = 0; j < HH; j++) b += bm[j];
            d_bmsum = b;
        }
    }
}

// ================= 1. degree histograms =================
__global__ void k_deg(const int* __restrict__ src, const int* __restrict__ dst) {
    int e = blockIdx.x * blockDim.x + threadIdx.x;
    if (e < EE) {
        atomicAdd(&d_degout[src[e]], 1);
        atomicAdd(&d_degin [dst[e]], 1);
    }
}

// ================= 2. scan phase 1: per-block sums ======================
__global__ void k_bsum() {
    __shared__ int ws[8];
    int i = blockIdx.x * 256 + threadIdx.x;
    int v = (i < NN) ? d_degin[i] : 0;
    #pragma unroll
    for (int o = 16; o; o >>= 1) v += __shfl_down_sync(0xffffffffu, v, o);
    int wid = threadIdx.x >> 5, lane = threadIdx.x & 31;
    if (lane == 0) ws[wid] = v;
    __syncthreads();
    if (threadIdx.x == 0) {
        int s = 0;
        #pragma unroll
        for (int w = 0; w < 8; w++) s += ws[w];
        d_bsum[blockIdx.x] = s;
    }
}

// ================= 3. scan phase 2: scan of 196 block sums ==============
__global__ void k_bscan() {
    __shared__ int ws[8];
    int t = threadIdx.x;
    int v = (t < SCAN_NB) ? d_bsum[t] : 0;
    int orig = v;
    int lane = t & 31, wid = t >> 5;
    #pragma unroll
    for (int o = 1; o < 32; o <<= 1) {
        int n = __shfl_up_sync(0xffffffffu, v, o);
        if (lane >= o) v += n;
    }
    if (lane == 31) ws[wid] = v;
    __syncthreads();
    if (wid == 0 && lane < 8) {
        int x = ws[lane];
        #pragma unroll
        for (int o = 1; o < 8; o <<= 1) {
            int n = __shfl_up_sync(0xffu, x, o);
            if (lane >= o) x += n;
        }
        ws[lane] = x;
    }
    __syncthreads();
    int incl = v + (wid ? ws[wid - 1] : 0);
    if (t < SCAN_NB) d_boff[t] = incl - orig;
    if (t == 0) d_rowptr[NN] = EE;
}

// ========== 4. scan phase 3: rowptr/cursor + norms (fused) ==============
__global__ void k_scan2() {
    __shared__ int ws[8];
    int i = blockIdx.x * 256 + threadIdx.x;
    int din = (i < NN) ? d_degin[i] : 0;
    int v = din;
    int lane = threadIdx.x & 31, wid = threadIdx.x >> 5;
    #pragma unroll
    for (int o = 1; o < 32; o <<= 1) {
        int n = __shfl_up_sync(0xffffffffu, v, o);
        if (lane >= o) v += n;
    }
    if (lane == 31) ws[wid] = v;
    __syncthreads();
    if (wid == 0 && lane < 8) {
        int x = ws[lane];
        #pragma unroll
        for (int o = 1; o < 8; o <<= 1) {
            int n = __shfl_up_sync(0xffu, x, o);
            if (lane >= o) x += n;
        }
        ws[lane] = x;
    }
    __syncthreads();
    int excl = v - din + (wid ? ws[wid - 1] : 0) + d_boff[blockIdx.x];
    if (i < NN) {
        d_rowptr[i] = excl;
        d_cursor[i] = excl;
        d_nin [i] = rsqrtf(fmaxf((float)din, 1.f));
        d_nout[i] = rsqrtf(fmaxf((float)d_degout[i], 1.f));
    }
}

// ================= 5. scatter edges into CSR(dst) =======================
__global__ void k_scatter(const int* __restrict__ src, const int* __restrict__ dst,
                          const int* __restrict__ perm) {
    int e = blockIdx.x * blockDim.x + threadIdx.x;
    if (e < EE) {
        int s = src[e], d = dst[e];
        int pos = atomicAdd(&d_cursor[d], 1);
        d_csrc[pos] = s;
        d_edge[pos] = make_int4(s, perm[s], __float_as_int(d_nout[s]), 0);
    }
}

// ====== 6. prepack W1 (fp16 hi/lo split) into mma B fragment layout =====
__global__ void k_bpack(const float* __restrict__ W1) {
    int t = blockIdx.x * 256 + threadIdx.x;
    if (t >= BFRAG_N) return;
    int l = t & 31;
    int r = t >> 5;
    int tt = r % 12; r /= 12;
    int s  = r % 4;  r /= 4;
    int c  = r % 8;
    int h  = r >> 3;
    int n  = tt * 8 + (l >> 2);
    int k0 = c * 64 + s * 16 + (l & 3) * 2;
    __half v[4];
    #pragma unroll
    for (int q = 0; q < 4; q++) {
        int k = k0 + (q >> 1) * 8 + (q & 1);
        float w = (k < FIN) ? W1[(size_t)k * HH + n] : 0.f;
        __half hi = __float2half_rn(w);
        v[q] = h ? __float2half_rn(w - __half2float(hi)) : hi;
    }
    uint2 out;
    __half2 p0 = __halves2half2(v[0], v[1]);
    __half2 p1 = __halves2half2(v[2], v[3]);
    out.x = *reinterpret_cast<uint32_t*>(&p0);
    out.y = *reinterpret_cast<uint32_t*>(&p1);
    d_Bfrag[t] = out;
}

// ====== 6b. prepack W2 (fp16 hi/lo split) into mma B fragment layout ====
__global__ void k_bpack2(const float* __restrict__ W2) {
    int t = blockIdx.x * 256 + threadIdx.x;
    if (t >= BFRAG2_N) return;
    int l = t & 31;
    int r = t >> 5;
    int tt = r % 12; r /= 12;
    int s  = r % 6;  r /= 6;
    int h  = r;
    int n  = tt * 8 + (l >> 2);
    int k0 = s * 16 + (l & 3) * 2;
    __half v[4];
    #pragma unroll
    for (int q = 0; q < 4; q++) {
        int k = k0 + (q >> 1) * 8 + (q & 1);
        float w = W2[(size_t)k * HH + n];
        __half hi = __float2half_rn(w);
        v[q] = h ? __float2half_rn(w - __half2float(hi)) : hi;
    }
    uint2 out;
    __half2 p0 = __halves2half2(v[0], v[1]);
    __half2 p1 = __halves2half2(v[2], v[3]);
    out.x = *reinterpret_cast<uint32_t*>(&p0);
    out.y = *reinterpret_cast<uint32_t*>(&p1);
    d_Bfrag2[t] = out;
}

// ================= 7. HMMA GEMM1: y = x @ W1 (fp16 out) =================
__global__ __launch_bounds__(256) void k_hmma(const float* __restrict__ x) {
    __shared__ __align__(16) __half Ah[128][72];
    __shared__ __align__(16) __half Al[128][72];
    int tid = threadIdx.x, lane = tid & 31, w = tid >> 5;
    int mw = w & 3, nw = w >> 2;
    int rowBase = blockIdx.x * 128;

    float acc[2][6][4];
    #pragma unroll
    for (int i = 0; i < 2; i++)
        #pragma unroll
        for (int j = 0; j < 6; j++)
            #pragma unroll
            for (int q = 0; q < 4; q++) acc[i][j][q] = 0.f;

    int r8 = lane & 7, sel = lane >> 3;
    int arow = mw * 32 + r8 + (sel & 1) * 8;
    int acol = (sel >> 1) * 8;
    uint32_t ah_base = smem_u32(&Ah[arow][acol]);
    uint32_t al_base = smem_u32(&Al[arow][acol]);

    for (int c = 0; c < 8; c++) {
        __syncthreads();
        #pragma unroll
        for (int i = 0; i < 8; i++) {
            int u = tid + 256 * i;
            int r = u >> 4, c4 = (u & 15) * 4;
            int gr = rowBase + r, gk = c * 64 + c4;
            float4 v = make_float4(0.f, 0.f, 0.f, 0.f);
            if (gr < NN && gk < FIN)
                v = *reinterpret_cast<const float4*>(&x[(size_t)gr * FIN + gk]);
            __half h0 = __float2half_rn(v.x), h1 = __float2half_rn(v.y);
            __half h2 = __float2half_rn(v.z), h3 = __float2half_rn(v.w);
            __half l0 = __float2half_rn(v.x - __half2float(h0));
            __half l1 = __float2half_rn(v.y - __half2float(h1));
            __half l2 = __float2half_rn(v.z - __half2float(h2));
            __half l3 = __float2half_rn(v.w - __half2float(h3));
            *reinterpret_cast<__half2*>(&Ah[r][c4 + 0]) = __halves2half2(h0, h1);
            *reinterpret_cast<__half2*>(&Ah[r][c4 + 2]) = __halves2half2(h2, h3);
            *reinterpret_cast<__half2*>(&Al[r][c4 + 0]) = __halves2half2(l0, l1);
            *reinterpret_cast<__half2*>(&Al[r][c4 + 2]) = __halves2half2(l2, l3);
        }
        __syncthreads();
        #pragma unroll
        for (int s = 0; s < 4; s++) {
            uint2 bh[6], bl[6];
            int bbase = ((c * 4 + s) * 12 + nw * 6) * 32 + lane;
            #pragma unroll
            for (int j = 0; j < 6; j++) {
                bh[j] = d_Bfrag[bbase + j * 32];
                bl[j] = d_Bfrag[12288 + bbase + j * 32];
            }
            uint32_t ah[2][4], al[2][4];
            #pragma unroll
            for (int i = 0; i < 2; i++) {
                ldmx4(ah[i], ah_base + (uint32_t)(i * 16 * 72 + s * 16) * 2u);
                ldmx4(al[i], al_base + (uint32_t)(i * 16 * 72 + s * 16) * 2u);
            }
            #pragma unroll
            for (int i = 0; i < 2; i++)
                #pragma unroll
                for (int j = 0; j < 6; j++) {
                    mma16816(acc[i][j], ah[i], bh[j]);
                    mma16816(acc[i][j], al[i], bh[j]);
                    mma16816(acc[i][j], ah[i], bl[j]);
                }
        }
    }
    #pragma unroll
    for (int i = 0; i < 2; i++) {
        int row = rowBase + mw * 32 + i * 16 + (lane >> 2);
        #pragma unroll
        for (int j = 0; j < 6; j++) {
            int col = nw * 48 + j * 8 + (lane & 3) * 2;
            if (row < NN)
                *reinterpret_cast<__half2*>(&d_yh[(size_t)row * HH + col])
                    = __floats2half2_rn(acc[i][j][0], acc[i][j][1]);
            if (row + 8 < NN)
                *reinterpret_cast<__half2*>(&d_yh[(size_t)(row + 8) * HH + col])
                    = __floats2half2_rn(acc[i][j][2], acc[i][j][3]);
        }
    }
}

// ========== 8. SpMM layer1: 3 loads/edge (1 uniform int4 + 2 uint2) =====
// lanes 0-23 active; lane owns cols [4*lane, 4*lane+3] of each 96-col view.
__global__ __launch_bounds__(256) void k_spmm1() {
    int node = blockIdx.x * 8 + (threadIdx.x >> 5);
    if (node >= NN) return;
    int lane = threadIdx.x & 31;
    bool act = lane < 24;
    int beg = d_rowptr[node], end = d_rowptr[node + 1];
    float a0 = 0.f, a1 = 0.f, a2 = 0.f, a3 = 0.f;
    float b0 = 0.f, b1 = 0.f, b2 = 0.f, b3 = 0.f;
    for (int j = beg; j < end; j++) {
        int4 e = d_edge[j];                    // warp-uniform LDG.128
        float w = __int_as_float(e.z);
        if (act) {
            uint2 v1 = *reinterpret_cast<const uint2*>(d_yh + (size_t)e.x * HH + lane * 4);
            uint2 v2 = *reinterpret_cast<const uint2*>(d_yh + (size_t)e.y * HH + lane * 4);
            __half2 p0 = *reinterpret_cast<__half2*>(&v1.x);
            __half2 p1 = *reinterpret_cast<__half2*>(&v1.y);
            __half2 q0 = *reinterpret_cast<__half2*>(&v2.x);
            __half2 q1 = *reinterpret_cast<__half2*>(&v2.y);
            a0 += w * __low2float(p0); a1 += w * __high2float(p0);
            a2 += w * __low2float(p1); a3 += w * __high2float(p1);
            b0 += w * __low2float(q0); b1 += w * __high2float(q0);
            b2 += w * __low2float(q1); b3 += w * __high2float(q1);
        }
    }
    if (act) {
        float* t = d_tf + (size_t)node * 192 + lane * 4;
        *reinterpret_cast<float4*>(t)      = make_float4(a0, a1, a2, a3);
        *reinterpret_cast<float4*>(t + 96) = make_float4(b0, b1, b2, b3);
    }
}

// ====== 9. layer-2 HMMA GEMM, fused PReLU prologue (fp32 in, fp16 out) ==
#define L2_STRIDE 104
#define L2_SMEM (2 * 128 * L2_STRIDE * 2 + (96 + 96 + 128 + 128) * 4)
__global__ __launch_bounds__(256) void k_l2mma(const float* __restrict__ bb1,
                                               const float* __restrict__ aa1) {
    extern __shared__ __align__(16) char sm8[];
    __half* Ah = reinterpret_cast<__half*>(sm8);
    __half* Al = Ah + 128 * L2_STRIDE;
    float* sb1 = reinterpret_cast<float*>(Al + 128 * L2_STRIDE);
    float* sa1 = sb1 + 96;
    float* sni = sa1 + 96;
    float* sno = sni + 128;

    int view = blockIdx.y;
    int tid = threadIdx.x, lane = tid & 31, w = tid >> 5;
    int mw = w & 3, nw = w >> 2;
    int rowBase = blockIdx.x * 128;

    if (tid < 128) {
        int gr = rowBase + tid;
        sni[tid] = (gr < NN) ? d_nin[gr]  : 0.f;
        sno[tid] = (gr < NN) ? d_nout[gr] : 0.f;
    }
    if (tid < 96)                 sb1[tid]      = bb1[tid];
    else if (tid >= 128 && tid < 224) sa1[tid - 128] = aa1[tid - 128];
    __syncthreads();

    #pragma unroll
    for (int i = 0; i < 12; i++) {
        int u = tid + 256 * i;          // 0..3071
        int r = u / 24, c4 = (u % 24) * 4;
        int gr = rowBase + r;
        float4 v = make_float4(0.f, 0.f, 0.f, 0.f);
        if (gr < NN) {
            v = *reinterpret_cast<const float4*>(&d_tf[(size_t)gr * 192 + view * 96 + c4]);
            float ni = sni[r], no = sno[r];
            float h;
            h = v.x * ni + sb1[c4 + 0]; h = (h >= 0.f) ? h : sa1[c4 + 0] * h; v.x = h * no;
            h = v.y * ni + sb1[c4 + 1]; h = (h >= 0.f) ? h : sa1[c4 + 1] * h; v.y = h * no;
            h = v.z * ni + sb1[c4 + 2]; h = (h >= 0.f) ? h : sa1[c4 + 2] * h; v.z = h * no;
            h = v.w * ni + sb1[c4 + 3]; h = (h >= 0.f) ? h : sa1[c4 + 3] * h; v.w = h * no;
        }
        __half h0 = __float2half_rn(v.x), h1 = __float2half_rn(v.y);
        __half h2 = __float2half_rn(v.z), h3 = __float2half_rn(v.w);
        __half l0 = __float2half_rn(v.x - __half2float(h0));
        __half l1 = __float2half_rn(v.y - __half2float(h1));
        __half l2 = __float2half_rn(v.z - __half2float(h2));
        __half l3 = __float2half_rn(v.w - __half2float(h3));
        int o = r * L2_STRIDE + c4;
        *reinterpret_cast<__half2*>(&Ah[o + 0]) = __halves2half2(h0, h1);
        *reinterpret_cast<__half2*>(&Ah[o + 2]) = __halves2half2(h2, h3);
        *reinterpret_cast<__half2*>(&Al[o + 0]) = __halves2half2(l0, l1);
        *reinterpret_cast<__half2*>(&Al[o + 2]) = __halves2half2(l2, l3);
    }
    __syncthreads();

    float acc[2][6][4];
    #pragma unroll
    for (int i = 0; i < 2; i++)
        #pragma unroll
        for (int j = 0; j < 6; j++)
            #pragma unroll
            for (int q = 0; q < 4; q++) acc[i][j][q] = 0.f;

    int r8 = lane & 7, sel = lane >> 3;
    int arow = mw * 32 + r8 + (sel & 1) * 8;
    int acol = (sel >> 1) * 8;
    uint32_t ah_base = smem_u32(&Ah[arow * L2_STRIDE + acol]);
    uint32_t al_base = smem_u32(&Al[arow * L2_STRIDE + acol]);

    #pragma unroll
    for (int s = 0; s < 6; s++) {
        uint2 bh[6], bl[6];
        int bbase = (s * 12 + nw * 6) * 32 + lane;
        #pragma unroll
        for (int j = 0; j < 6; j++) {
            bh[j] = d_Bfrag2[bbase + j * 32];
            bl[j] = d_Bfrag2[2304 + bbase + j * 32];
        }
        uint32_t ah[2][4], al[2][4];
        #pragma unroll
        for (int i = 0; i < 2; i++) {
            ldmx4(ah[i], ah_base + (uint32_t)(i * 16 * L2_STRIDE + s * 16) * 2u);
            ldmx4(al[i], al_base + (uint32_t)(i * 16 * L2_STRIDE + s * 16) * 2u);
        }
        #pragma unroll
        for (int i = 0; i < 2; i++)
            #pragma unroll
            for (int j = 0; j < 6; j++) {
                mma16816(acc[i][j], ah[i], bh[j]);
                mma16816(acc[i][j], al[i], bh[j]);
                mma16816(acc[i][j], ah[i], bl[j]);
            }
    }

    #pragma unroll
    for (int i = 0; i < 2; i++) {
        int row = rowBase + mw * 32 + i * 16 + (lane >> 2);
        #pragma unroll
        for (int j = 0; j < 6; j++) {
            int col = nw * 48 + j * 8 + (lane & 3) * 2;
            if (row < NN)
                *reinterpret_cast<__half2*>(&d_gh[(size_t)row * 192 + view * 96 + col])
                    = __floats2half2_rn(acc[i][j][0], acc[i][j][1]);
            if (row + 8 < NN)
                *reinterpret_cast<__half2*>(&d_gh[(size_t)(row + 8) * 192 + view * 96 + col])
                    = __floats2half2_rn(acc[i][j][2], acc[i][j][3]);
        }
    }
}

// ====== 10. SpMM layer2: 2 loads/edge (1 uniform + 1 uint4 gather) ======
// lanes 0-23: lane owns halves [8*lane, 8*lane+7] of the 192-wide g row.
// lanes 0-11 -> view1 cols 8l..8l+7; lanes 12-23 -> view2 cols 8(l-12)..
__global__ __launch_bounds__(256) void k_spmm2(const float* __restrict__ bb2,
                                               const float* __restrict__ aa2,
                                               float* __restrict__ out) {
    int node = blockIdx.x * 8 + (threadIdx.x >> 5);
    if (node >= NN) return;
    int lane = threadIdx.x & 31;
    bool act = lane < 24;
    int cb = (lane * 8) % 96;                  // col base within the 96-col space
    float bc[8], ac[8], wc[8];
    if (act) {
        #pragma unroll
        for (int q = 0; q < 8; q++) {
            bc[q] = bb2[cb + q];
            ac[q] = aa2[cb + q];
            wc[q] = d_wmsum[cb + q];
        }
    }
    int beg = d_rowptr[node], end = d_rowptr[node + 1];
    float acc[8] = {0.f, 0.f, 0.f, 0.f, 0.f, 0.f, 0.f, 0.f};
    for (int j = beg; j < end; j++) {
        int s = d_csrc[j];                     // warp-uniform LDG.32
        if (act) {
            uint4 v = *reinterpret_cast<const uint4*>(d_gh + (size_t)s * 192 + lane * 8);
            __half2 p0 = *reinterpret_cast<__half2*>(&v.x);
            __half2 p1 = *reinterpret_cast<__half2*>(&v.y);
            __half2 p2 = *reinterpret_cast<__half2*>(&v.z);
            __half2 p3 = *reinterpret_cast<__half2*>(&v.w);
            acc[0] += __low2float(p0); acc[1] += __high2float(p0);
            acc[2] += __low2float(p1); acc[3] += __high2float(p1);
            acc[4] += __low2float(p2); acc[5] += __high2float(p2);
            acc[6] += __low2float(p3); acc[7] += __high2float(p3);
        }
    }
    float ni = d_nin[node];
    float sv = 0.f;
    if (act) {
        #pragma unroll
        for (int q = 0; q < 8; q++) {
            float v = acc[q] * ni + bc[q];
            v = (v >= 0.f) ? v : ac[q] * v;
            sv += v * wc[q];
        }
    }
    float s1 = (lane < 12) ? sv : 0.f;
    float s2 = (lane >= 12 && lane < 24) ? sv : 0.f;
    #pragma unroll
    for (int o = 16; o; o >>= 1) {
        s1 += __shfl_xor_sync(0xffffffffu, s1, o);
        s2 += __shfl_xor_sync(0xffffffffu, s2, o);
    }
    if (lane == 0) {
        float bsum = d_bmsum;
        out[node]      = s1 + bsum;
        out[NN + node] = s2 + bsum;
    }
}

// ================= launch =================
extern "C" void kernel_launch(void* const* d_in, const int* in_sizes, int n_in,
                              void* d_out, int out_size) {
    (void)in_sizes; (void)n_in; (void)out_size;
    const float* x    = (const float*)d_in[0];
    const int*   src  = (const int*)  d_in[1];
    const int*   dst  = (const int*)  d_in[2];
    const int*   perm = (const int*)  d_in[3];
    const float* W1   = (const float*)d_in[4];
    const float* b1   = (const float*)d_in[5];
    const float* a1   = (const float*)d_in[6];
    const float* W2   = (const float*)d_in[7];
    const float* b2   = (const float*)d_in[8];
    const float* a2   = (const float*)d_in[9];
    const float* Wm   = (const float*)d_in[10];
    const float* bm   = (const float*)d_in[11];
    float* out = (float*)d_out;

    static int attr_done = 0;
    if (!attr_done) {
        cudaFuncSetAttribute(k_l2mma, cudaFuncAttributeMaxDynamicSharedMemorySize, L2_SMEM);
        attr_done = 1;
    }

    k_bpack  <<<(BFRAG_N + 255) / 256, 256>>>(W1);
    k_bpack2 <<<(BFRAG2_N + 255) / 256, 256>>>(W2);
    k_prep   <<<(NN + 255) / 256, 256>>>(Wm, bm);
    k_deg    <<<(EE + 255) / 256, 256>>>(src, dst);
    k_bsum   <<<SCAN_NB, 256>>>();
    k_bscan  <<<1, 256>>>();
    k_scan2  <<<SCAN_NB, 256>>>();
    k_scatter<<<(EE + 255) / 256, 256>>>(src, dst, perm);

    k_hmma   <<<(NN + 127) / 128, 256>>>(x);
    k_spmm1  <<<(NN + 7) / 8, 256>>>();
    dim3 gl2((NN + 127) / 128, 2);
    k_l2mma  <<<gl2, 256, L2_SMEM>>>(b1, a1);
    k_spmm2  <<<(NN + 7) / 8, 256>>>(b2, a2, out);
}

// round 15
// speedup vs baseline: 1.0948x; 1.0948x over previous
#include <cuda_runtime.h>
#include <cuda_fp16.h>
#include <cstdint>

#define NN  50000
#define EE  800000
#define FIN 500
#define HH  96

typedef unsigned long long ull;

// ================= device scratch =================
__device__ __half d_yh[(size_t)NN * HH];      // x @ W1, fp16
__device__ float  d_t1[(size_t)NN * HH];
__device__ float  d_t2[(size_t)NN * HH];
__device__ float  d_g1[(size_t)NN * HH];
__device__ float  d_g2[(size_t)NN * HH];
__device__ int    d_degout[NN];
__device__ int    d_degin [NN];
__device__ float  d_nout[NN];
__device__ float  d_nin [NN];
__device__ int    d_rowptr[NN + 1];
__device__ int    d_cursor[NN];
__device__ int    d_csrc [EE];                // src per CSR slot (spmm2)
__device__ int4   d_edge [EE];                // {src, perm[src], w_bits, 0} (spmm1)
__device__ float  d_wmsum[HH];
__device__ float  d_bmsum;
// prepacked W1 fragments: [h(2)][chunk(8)][kstep(4)][ntile(12)][lane(32)] uint2
#define BFRAG_N 24576
__device__ uint2  d_Bfrag[BFRAG_N];
// prepacked W2 fragments: [h(2)][kstep(6)][ntile(12)][lane(32)] uint2
#define BFRAG2_N 4608
__device__ uint2  d_Bfrag2[BFRAG2_N];
// scan temporaries
#define SCAN_NB 196
__device__ int    d_bsum[SCAN_NB];
__device__ int    d_boff[SCAN_NB];

// ================= mma helpers =================
__device__ __forceinline__ uint32_t smem_u32(const void* p) {
    uint32_t a;
    asm("{ .reg .u64 t; cvta.to.shared.u64 t, %1; cvt.u32.u64 %0, t; }" : "=r"(a) : "l"(p));
    return a;
}
__device__ __forceinline__ void ldmx4(uint32_t* r, uint32_t addr) {
    asm volatile("ldmatrix.sync.aligned.m8n8.x4.shared.b16 {%0,%1,%2,%3}, [%4];"
        : "=r"(r[0]), "=r"(r[1]), "=r"(r[2]), "=r"(r[3]) : "r"(addr));
}
__device__ __forceinline__ void mma16816(float* d, const uint32_t* a, uint2 b) {
    asm volatile("mma.sync.aligned.m16n8k16.row.col.f32.f16.f16.f32 "
        "{%0,%1,%2,%3}, {%4,%5,%6,%7}, {%8,%9}, {%0,%1,%2,%3};"
        : "+f"(d[0]), "+f"(d[1]), "+f"(d[2]), "+f"(d[3])
        : "r"(a[0]), "r"(a[1]), "r"(a[2]), "r"(a[3]), "r"(b.x), "r"(b.y));
}

// ================= 0. prep: zero degrees, Wm row-sums =================
__global__ void k_prep(const float* __restrict__ Wm, const float* __restrict__ bm) {
    int i = blockIdx.x * blockDim.x + threadIdx.x;
    if (i < NN) { d_degout[i] = 0; d_degin[i] = 0; }
    if (blockIdx.x == 0 && threadIdx.x < HH) {
        float s = 0.f;
        #pragma unroll 4
        for (int j = 0; j < HH; j++) s += Wm[threadIdx.x * HH + j];
        d_wmsum[threadIdx.x] = s;
        if (threadIdx.x == 0) {
            float b = 0.f;
            for (int j = 0; j < HH; j++) b += bm[j];
            d_bmsum = b;
        }
    }
}

// ================= 1. degree histograms =================
__global__ void k_deg(const int* __restrict__ src, const int* __restrict__ dst) {
    int e = blockIdx.x * blockDim.x + threadIdx.x;
    if (e < EE) {
        atomicAdd(&d_degout[src[e]], 1);
        atomicAdd(&d_degin [dst[e]], 1);
    }
}

// ================= 2. scan phase 1: per-block sums ======================
__global__ void k_bsum() {
    __shared__ int ws[8];
    int i = blockIdx.x * 256 + threadIdx.x;
    int v = (i < NN) ? d_degin[i] : 0;
    #pragma unroll
    for (int o = 16; o; o >>= 1) v += __shfl_down_sync(0xffffffffu, v, o);
    int wid = threadIdx.x >> 5, lane = threadIdx.x & 31;
    if (lane == 0) ws[wid] = v;
    __syncthreads();
    if (threadIdx.x == 0) {
        int s = 0;
        #pragma unroll
        for (int w = 0; w < 8; w++) s += ws[w];
        d_bsum[blockIdx.x] = s;
    }
}

// ================= 3. scan phase 2: scan of 196 block sums ==============
__global__ void k_bscan() {
    __shared__ int ws[8];
    int t = threadIdx.x;
    int v = (t < SCAN_NB) ? d_bsum[t] : 0;
    int orig = v;
    int lane = t & 31, wid = t >> 5;
    #pragma unroll
    for (int o = 1; o < 32; o <<= 1) {
        int n = __shfl_up_sync(0xffffffffu, v, o);
        if (lane >= o) v += n;
    }
    if (lane == 31) ws[wid] = v;
    __syncthreads();
    if (wid == 0 && lane < 8) {
        int x = ws[lane];
        #pragma unroll
        for (int o = 1; o < 8; o <<= 1) {
            int n = __shfl_up_sync(0xffu, x, o);
            if (lane >= o) x += n;
        }
        ws[lane] = x;
    }
    __syncthreads();
    int incl = v + (wid ? ws[wid - 1] : 0);
    if (t < SCAN_NB) d_boff[t] = incl - orig;
    if (t == 0) d_rowptr[NN] = EE;
}

// ========== 4. scan phase 3: rowptr/cursor + norms (fused) ==============
__global__ void k_scan2() {
    __shared__ int ws[8];
    int i = blockIdx.x * 256 + threadIdx.x;
    int din = (i < NN) ? d_degin[i] : 0;
    int v = din;
    int lane = threadIdx.x & 31, wid = threadIdx.x >> 5;
    #pragma unroll
    for (int o = 1; o < 32; o <<= 1) {
        int n = __shfl_up_sync(0xffffffffu, v, o);
        if (lane >= o) v += n;
    }
    if (lane == 31) ws[wid] = v;
    __syncthreads();
    if (wid == 0 && lane < 8) {
        int x = ws[lane];
        #pragma unroll
        for (int o = 1; o < 8; o <<= 1) {
            int n = __shfl_up_sync(0xffu, x, o);
            if (lane >= o) x += n;
        }
        ws[lane] = x;
    }
    __syncthreads();
    int excl = v - din + (wid ? ws[wid - 1] : 0) + d_boff[blockIdx.x];
    if (i < NN) {
        d_rowptr[i] = excl;
        d_cursor[i] = excl;
        d_nin [i] = rsqrtf(fmaxf((float)din, 1.f));
        d_nout[i] = rsqrtf(fmaxf((float)d_degout[i], 1.f));
    }
}

// ================= 5. scatter edges into CSR(dst) =======================
__global__ void k_scatter(const int* __restrict__ src, const int* __restrict__ dst,
                          const int* __restrict__ perm) {
    int e = blockIdx.x * blockDim.x + threadIdx.x;
    if (e < EE) {
        int s = src[e], d = dst[e];
        int pos = atomicAdd(&d_cursor[d], 1);
        d_csrc[pos] = s;
        d_edge[pos] = make_int4(s, perm[s], __float_as_int(d_nout[s]), 0);
    }
}

// ====== 6. prepack W1 (fp16 hi/lo split) into mma B fragment layout =====
__global__ void k_bpack(const float* __restrict__ W1) {
    int t = blockIdx.x * 256 + threadIdx.x;
    if (t >= BFRAG_N) return;
    int l = t & 31;
    int r = t >> 5;
    int tt = r % 12; r /= 12;
    int s  = r % 4;  r /= 4;
    int c  = r % 8;
    int h  = r >> 3;
    int n  = tt * 8 + (l >> 2);
    int k0 = c * 64 + s * 16 + (l & 3) * 2;
    __half v[4];
    #pragma unroll
    for (int q = 0; q < 4; q++) {
        int k = k0 + (q >> 1) * 8 + (q & 1);
        float w = (k < FIN) ? W1[(size_t)k * HH + n] : 0.f;
        __half hi = __float2half_rn(w);
        v[q] = h ? __float2half_rn(w - __half2float(hi)) : hi;
    }
    uint2 out;
    __half2 p0 = __halves2half2(v[0], v[1]);
    __half2 p1 = __halves2half2(v[2], v[3]);
    out.x = *reinterpret_cast<uint32_t*>(&p0);
    out.y = *reinterpret_cast<uint32_t*>(&p1);
    d_Bfrag[t] = out;
}

// ====== 6b. prepack W2 (fp16 hi/lo split) into mma B fragment layout ====
__global__ void k_bpack2(const float* __restrict__ W2) {
    int t = blockIdx.x * 256 + threadIdx.x;
    if (t >= BFRAG2_N) return;
    int l = t & 31;
    int r = t >> 5;
    int tt = r % 12; r /= 12;
    int s  = r % 6;  r /= 6;
    int h  = r;
    int n  = tt * 8 + (l >> 2);
    int k0 = s * 16 + (l & 3) * 2;
    __half v[4];
    #pragma unroll
    for (int q = 0; q < 4; q++) {
        int k = k0 + (q >> 1) * 8 + (q & 1);
        float w = W2[(size_t)k * HH + n];
        __half hi = __float2half_rn(w);
        v[q] = h ? __float2half_rn(w - __half2float(hi)) : hi;
    }
    uint2 out;
    __half2 p0 = __halves2half2(v[0], v[1]);
    __half2 p1 = __halves2half2(v[2], v[3]);
    out.x = *reinterpret_cast<uint32_t*>(&p0);
    out.y = *reinterpret_cast<uint32_t*>(&p1);
    d_Bfrag2[t] = out;
}

// ================= 7. HMMA GEMM1: y = x @ W1 (fp16 out) =================
__global__ __launch_bounds__(256) void k_hmma(const float* __restrict__ x) {
    __shared__ __align__(16) __half Ah[128][72];
    __shared__ __align__(16) __half Al[128][72];
    int tid = threadIdx.x, lane = tid & 31, w = tid >> 5;
    int mw = w & 3, nw = w >> 2;
    int rowBase = blockIdx.x * 128;

    float acc[2][6][4];
    #pragma unroll
    for (int i = 0; i < 2; i++)
        #pragma unroll
        for (int j = 0; j < 6; j++)
            #pragma unroll
            for (int q = 0; q < 4; q++) acc[i][j][q] = 0.f;

    int r8 = lane & 7, sel = lane >> 3;
    int arow = mw * 32 + r8 + (sel & 1) * 8;
    int acol = (sel >> 1) * 8;
    uint32_t ah_base = smem_u32(&Ah[arow][acol]);
    uint32_t al_base = smem_u32(&Al[arow][acol]);

    for (int c = 0; c < 8; c++) {
        __syncthreads();
        #pragma unroll
        for (int i = 0; i < 8; i++) {
            int u = tid + 256 * i;
            int r = u >> 4, c4 = (u & 15) * 4;
            int gr = rowBase + r, gk = c * 64 + c4;
            float4 v = make_float4(0.f, 0.f, 0.f, 0.f);
            if (gr < NN && gk < FIN)
                v = *reinterpret_cast<const float4*>(&x[(size_t)gr * FIN + gk]);
            __half h0 = __float2half_rn(v.x), h1 = __float2half_rn(v.y);
            __half h2 = __float2half_rn(v.z), h3 = __float2half_rn(v.w);
            __half l0 = __float2half_rn(v.x - __half2float(h0));
            __half l1 = __float2half_rn(v.y - __half2float(h1));
            __half l2 = __float2half_rn(v.z - __half2float(h2));
            __half l3 = __float2half_rn(v.w - __half2float(h3));
            *reinterpret_cast<__half2*>(&Ah[r][c4 + 0]) = __halves2half2(h0, h1);
            *reinterpret_cast<__half2*>(&Ah[r][c4 + 2]) = __halves2half2(h2, h3);
            *reinterpret_cast<__half2*>(&Al[r][c4 + 0]) = __halves2half2(l0, l1);
            *reinterpret_cast<__half2*>(&Al[r][c4 + 2]) = __halves2half2(l2, l3);
        }
        __syncthreads();
        #pragma unroll
        for (int s = 0; s < 4; s++) {
            uint2 bh[6], bl[6];
            int bbase = ((c * 4 + s) * 12 + nw * 6) * 32 + lane;
            #pragma unroll
            for (int j = 0; j < 6; j++) {
                bh[j] = d_Bfrag[bbase + j * 32];
                bl[j] = d_Bfrag[12288 + bbase + j * 32];
            }
            uint32_t ah[2][4], al[2][4];
            #pragma unroll
            for (int i = 0; i < 2; i++) {
                ldmx4(ah[i], ah_base + (uint32_t)(i * 16 * 72 + s * 16) * 2u);
                ldmx4(al[i], al_base + (uint32_t)(i * 16 * 72 + s * 16) * 2u);
            }
            #pragma unroll
            for (int i = 0; i < 2; i++)
                #pragma unroll
                for (int j = 0; j < 6; j++) {
                    mma16816(acc[i][j], ah[i], bh[j]);
                    mma16816(acc[i][j], al[i], bh[j]);
                    mma16816(acc[i][j], ah[i], bl[j]);
                }
        }
    }
    #pragma unroll
    for (int i = 0; i < 2; i++) {
        int row = rowBase + mw * 32 + i * 16 + (lane >> 2);
        #pragma unroll
        for (int j = 0; j < 6; j++) {
            int col = nw * 48 + j * 8 + (lane & 3) * 2;
            if (row < NN)
                *reinterpret_cast<__half2*>(&d_yh[(size_t)row * HH + col])
                    = __floats2half2_rn(acc[i][j][0], acc[i][j][1]);
            if (row + 8 < NN)
                *reinterpret_cast<__half2*>(&d_yh[(size_t)(row + 8) * HH + col])
                    = __floats2half2_rn(acc[i][j][2], acc[i][j][3]);
        }
    }
}

// ========== 8. SpMM layer1 (dual view, 32-lane gathers, int4 meta) ======
__global__ __launch_bounds__(256) void k_spmm1() {
    int node = blockIdx.x * (blockDim.x >> 5) + (threadIdx.x >> 5);
    if (node >= NN) return;
    int lane = threadIdx.x & 31;
    int beg = d_rowptr[node], end = d_rowptr[node + 1];
    float a0 = 0.f, a1 = 0.f, a2 = 0.f, b0 = 0.f, b1 = 0.f, b2 = 0.f;
    for (int j = beg; j < end; j++) {
        int4 e = d_edge[j];                    // one warp-uniform LDG.128
        float w = __int_as_float(e.z);
        const __half* yr = d_yh + (size_t)e.x * HH;
        const __half* pr = d_yh + (size_t)e.y * HH;
        a0 += w * __half2float(yr[lane]);
        a1 += w * __half2float(yr[lane + 32]);
        a2 += w * __half2float(yr[lane + 64]);
        b0 += w * __half2float(pr[lane]);
        b1 += w * __half2float(pr[lane + 32]);
        b2 += w * __half2float(pr[lane + 64]);
    }
    float* t1 = d_t1 + (size_t)node * HH;
    float* t2 = d_t2 + (size_t)node * HH;
    t1[lane] = a0; t1[lane + 32] = a1; t1[lane + 64] = a2;
    t2[lane] = b0; t2[lane + 32] = b1; t2[lane + 64] = b2;
}

// ====== 9. layer-2 HMMA GEMM, fused PReLU prologue (fp32 in/out) ========
#define L2_STRIDE 104
#define L2_SMEM (2 * 128 * L2_STRIDE * 2 + (96 + 96 + 128 + 128) * 4)
__global__ __launch_bounds__(256) void k_l2mma(const float* __restrict__ bb1,
                                               const float* __restrict__ aa1) {
    extern __shared__ __align__(16) char sm8[];
    __half* Ah = reinterpret_cast<__half*>(sm8);
    __half* Al = Ah + 128 * L2_STRIDE;
    float* sb1 = reinterpret_cast<float*>(Al + 128 * L2_STRIDE);
    float* sa1 = sb1 + 96;
    float* sni = sa1 + 96;
    float* sno = sni + 128;

    const float* t = blockIdx.y ? d_t2 : d_t1;
    float*       g = blockIdx.y ? d_g2 : d_g1;
    int tid = threadIdx.x, lane = tid & 31, w = tid >> 5;
    int mw = w & 3, nw = w >> 2;
    int rowBase = blockIdx.x * 128;

    if (tid < 128) {
        int gr = rowBase + tid;
        sni[tid] = (gr < NN) ? d_nin[gr]  : 0.f;
        sno[tid] = (gr < NN) ? d_nout[gr] : 0.f;
    }
    if (tid < 96)                 sb1[tid]      = bb1[tid];
    else if (tid >= 128 && tid < 224) sa1[tid - 128] = aa1[tid - 128];
    __syncthreads();

    #pragma unroll
    for (int i = 0; i < 12; i++) {
        int u = tid + 256 * i;          // 0..3071
        int r = u / 24, c4 = (u % 24) * 4;
        int gr = rowBase + r;
        float4 v = make_float4(0.f, 0.f, 0.f, 0.f);
        if (gr < NN) {
            v = *reinterpret_cast<const float4*>(&t[(size_t)gr * HH + c4]);
            float ni = sni[r], no = sno[r];
            float h;
            h = v.x * ni + sb1[c4 + 0]; h = (h >= 0.f) ? h : sa1[c4 + 0] * h; v.x = h * no;
            h = v.y * ni + sb1[c4 + 1]; h = (h >= 0.f) ? h : sa1[c4 + 1] * h; v.y = h * no;
            h = v.z * ni + sb1[c4 + 2]; h = (h >= 0.f) ? h : sa1[c4 + 2] * h; v.z = h * no;
            h = v.w * ni + sb1[c4 + 3]; h = (h >= 0.f) ? h : sa1[c4 + 3] * h; v.w = h * no;
        }
        __half h0 = __float2half_rn(v.x), h1 = __float2half_rn(v.y);
        __half h2 = __float2half_rn(v.z), h3 = __float2half_rn(v.w);
        __half l0 = __float2half_rn(v.x - __half2float(h0));
        __half l1 = __float2half_rn(v.y - __half2float(h1));
        __half l2 = __float2half_rn(v.z - __half2float(h2));
        __half l3 = __float2half_rn(v.w - __half2float(h3));
        int o = r * L2_STRIDE + c4;
        *reinterpret_cast<__half2*>(&Ah[o + 0]) = __halves2half2(h0, h1);
        *reinterpret_cast<__half2*>(&Ah[o + 2]) = __halves2half2(h2, h3);
        *reinterpret_cast<__half2*>(&Al[o + 0]) = __halves2half2(l0, l1);
        *reinterpret_cast<__half2*>(&Al[o + 2]) = __halves2half2(l2, l3);
    }
    __syncthreads();

    float acc[2][6][4];
    #pragma unroll
    for (int i = 0; i < 2; i++)
        #pragma unroll
        for (int j = 0; j < 6; j++)
            #pragma unroll
            for (int q = 0; q < 4; q++) acc[i][j][q] = 0.f;

    int r8 = lane & 7, sel = lane >> 3;
    int arow = mw * 32 + r8 + (sel & 1) * 8;
    int acol = (sel >> 1) * 8;
    uint32_t ah_base = smem_u32(&Ah[arow * L2_STRIDE + acol]);
    uint32_t al_base = smem_u32(&Al[arow * L2_STRIDE + acol]);

    #pragma unroll
    for (int s = 0; s < 6; s++) {
        uint2 bh[6], bl[6];
        int bbase = (s * 12 + nw * 6) * 32 + lane;
        #pragma unroll
        for (int j = 0; j < 6; j++) {
            bh[j] = d_Bfrag2[bbase + j * 32];
            bl[j] = d_Bfrag2[2304 + bbase + j * 32];
        }
        uint32_t ah[2][4], al[2][4];
        #pragma unroll
        for (int i = 0; i < 2; i++) {
            ldmx4(ah[i], ah_base + (uint32_t)(i * 16 * L2_STRIDE + s * 16) * 2u);
            ldmx4(al[i], al_base + (uint32_t)(i * 16 * L2_STRIDE + s * 16) * 2u);
        }
        #pragma unroll
        for (int i = 0; i < 2; i++)
            #pragma unroll
            for (int j = 0; j < 6; j++) {
                mma16816(acc[i][j], ah[i], bh[j]);
                mma16816(acc[i][j], al[i], bh[j]);
                mma16816(acc[i][j], ah[i], bl[j]);
            }
    }

    #pragma unroll
    for (int i = 0; i < 2; i++) {
        int row = rowBase + mw * 32 + i * 16 + (lane >> 2);
        #pragma unroll
        for (int j = 0; j < 6; j++) {
            int col = nw * 48 + j * 8 + (lane & 3) * 2;
            if (row < NN)
                *reinterpret_cast<float2*>(&g[(size_t)row * HH + col])
                    = make_float2(acc[i][j][0], acc[i][j][1]);
            if (row + 8 < NN)
                *reinterpret_cast<float2*>(&g[(size_t)(row + 8) * HH + col])
                    = make_float2(acc[i][j][2], acc[i][j][3]);
        }
    }
}

// ====== 10. SpMM layer2 + fused PReLU + Wm-rowsum dot ===================
__global__ __launch_bounds__(256) void k_spmm2(const float* __restrict__ bb2,
                                               const float* __restrict__ aa2,
                                               float* __restrict__ out) {
    int node = blockIdx.x * (blockDim.x >> 5) + (threadIdx.x >> 5);
    if (node >= NN) return;
    int lane = threadIdx.x & 31;
    int beg = d_rowptr[node], end = d_rowptr[node + 1];
    float a0 = 0.f, a1 = 0.f, a2 = 0.f, b0 = 0.f, b1 = 0.f, b2 = 0.f;
    for (int j = beg; j < end; j++) {
        int s = d_csrc[j];
        const float* g1 = d_g1 + (size_t)s * HH;
        const float* g2 = d_g2 + (size_t)s * HH;
        a0 += g1[lane]; a1 += g1[lane + 32]; a2 += g1[lane + 64];
        b0 += g2[lane]; b1 += g2[lane + 32]; b2 += g2[lane + 64];
    }
    float ni = d_nin[node];
    float s1 = 0.f, s2 = 0.f;
    float accs1[3] = {a0, a1, a2};
    float accs2[3] = {b0, b1, b2};
    #pragma unroll
    for (int tcol = 0; tcol < 3; tcol++) {
        int c = lane + 32 * tcol;
        float bc = bb2[c], ac = aa2[c], wc = d_wmsum[c];
        float v1 = accs1[tcol] * ni + bc; v1 = (v1 >= 0.f) ? v1 : ac * v1;
        float v2 = accs2[tcol] * ni + bc; v2 = (v2 >= 0.f) ? v2 : ac * v2;
        s1 += v1 * wc;
        s2 += v2 * wc;
    }
    #pragma unroll
    for (int o = 16; o; o >>= 1) {
        s1 += __shfl_xor_sync(0xffffffffu, s1, o);
        s2 += __shfl_xor_sync(0xffffffffu, s2, o);
    }
    if (lane == 0) {
        float bsum = d_bmsum;
        out[node]      = s1 + bsum;
        out[NN + node] = s2 + bsum;
    }
}

// ================= launch =================
// Order chosen so k_hmma is the 6th launch (ncu window -s 5 -c 1).
extern "C" void kernel_launch(void* const* d_in, const int* in_sizes, int n_in,
                              void* d_out, int out_size) {
    (void)in_sizes; (void)n_in; (void)out_size;
    const float* x    = (const float*)d_in[0];
    const int*   src  = (const int*)  d_in[1];
    const int*   dst  = (const int*)  d_in[2];
    const int*   perm = (const int*)  d_in[3];
    const float* W1   = (const float*)d_in[4];
    const float* b1   = (const float*)d_in[5];
    const float* a1   = (const float*)d_in[6];
    const float* W2   = (const float*)d_in[7];
    const float* b2   = (const float*)d_in[8];
    const float* a2   = (const float*)d_in[9];
    const float* Wm   = (const float*)d_in[10];
    const float* bm   = (const float*)d_in[11];
    float* out = (float*)d_out;

    static int attr_done = 0;
    if (!attr_done) {
        cudaFuncSetAttribute(k_l2mma, cudaFuncAttributeMaxDynamicSharedMemorySize, L2_SMEM);
        attr_done = 1;
    }

    k_bpack2 <<<(BFRAG2_N + 255) / 256, 256>>>(W2);          // 1
    k_prep   <<<(NN + 255) / 256, 256>>>(Wm, bm);            // 2
    k_deg    <<<(EE + 255) / 256, 256>>>(src, dst);          // 3
    k_bsum   <<<SCAN_NB, 256>>>();                           // 4
    k_bpack  <<<(BFRAG_N + 255) / 256, 256>>>(W1);           // 5
    k_hmma   <<<(NN + 127) / 128, 256>>>(x);                 // 6 <- profiled
    k_bscan  <<<1, 256>>>();                                 // 7
    k_scan2  <<<SCAN_NB, 256>>>();                           // 8
    k_scatter<<<(EE + 255) / 256, 256>>>(src, dst, perm);    // 9
    k_spmm1  <<<(NN + 7) / 8, 256>>>();                      // 10
    dim3 gl2((NN + 127) / 128, 2);
    k_l2mma  <<<gl2, 256, L2_SMEM>>>(b1, a1);                // 11
    k_spmm2  <<<(NN + 7) / 8, 256>>>(b2, a2, out);           // 12
}